// round 1
// baseline (speedup 1.0000x reference)
#include <cuda_runtime.h>
#include <math.h>

#define LL 12
#define BB 4
#define CC 768
#define DD 128
#define HWN 256
#define MAXN 30016

// ---------------- scratch (static device allocations; no cudaMalloc) ----------------
__device__ float d_feat[LL * BB * HWN * DD];   // [l][b][pix][d], 6.29 MB
__device__ float d_gb[LL * BB * DD];           // [l][b][d]
__device__ int   d_pixv[MAXN * 4];
__device__ float d_pwv[MAXN * 4];
__device__ float d_wl[MAXN * LL];
__device__ float d_sscale[MAXN];
__device__ float d_regE;
__device__ float d_regS;

__global__ void init_kernel() {
    d_regE = 0.0f;
    d_regS = 0.0f;
}

__device__ __forceinline__ float gelu_exact(float x) {
    // jax.nn.gelu(approximate=False) = x * Phi(x)
    return x * normcdff(x);
}

// ---------------- selector: PE + 3 MLP heads, tile of 32 points per block ----------------
__global__ __launch_bounds__(256) void selector_kernel(
    const float* __restrict__ coords,
    const float* __restrict__ W1, const float* __restrict__ b1,
    const float* __restrict__ W2, const float* __restrict__ b2,
    const float* __restrict__ spaceW3, const float* __restrict__ layerW3,
    const float* __restrict__ scaleW3, int N)
{
    __shared__ __align__(16) float peS[192][36];  // [k][n], padded
    __shared__ __align__(16) float hS[128][36];   // [k][n], reused h1 -> h2 per head
    __shared__ float outS[32][12];
    __shared__ float entS[32];
    __shared__ float penS[32];

    const int t = threadIdx.x;
    const int n0 = blockIdx.x * 32;

    // ---- positional encoding into smem ----
    for (int idx = t; idx < 192 * 32; idx += 256) {
        int n = idx & 31;
        int j = idx >> 5;          // 0..191
        int c = j >> 6;            // coordinate 0..2
        int r = j & 63;            // 0..63 (sin first 32, cos next 32)
        int f = r & 31;
        float freq = exp2f((float)f * (8.0f / 31.0f)) * 3.14159265358979323846f;
        float x = (n0 + n < N) ? coords[(n0 + n) * 3 + c] : 0.0f;
        float a = x * freq;
        peS[j][n] = (r < 32) ? sinf(a) : cosf(a);
    }
    __syncthreads();

    const int nb = (t & 7) * 4;    // point sub-tile (4 of 32)
    const int db = (t >> 3) * 4;   // hidden-dim sub-tile (4 of 128)

    for (int head = 0; head < 3; head++) {
        const float* w1 = W1 + head * 192 * 128;
        const float* w2 = W2 + head * 128 * 128;

        // ---- phase 1: h1 = gelu(pe @ W1 + b1), micro-tile 4n x 4d ----
        float acc[4][4];
        #pragma unroll
        for (int i = 0; i < 4; i++)
            #pragma unroll
            for (int j = 0; j < 4; j++) acc[i][j] = 0.0f;

        for (int k = 0; k < 192; k++) {
            float4 w = *(const float4*)(w1 + k * 128 + db);
            float4 p = *(const float4*)(&peS[k][nb]);
            float pv[4] = {p.x, p.y, p.z, p.w};
            float wv[4] = {w.x, w.y, w.z, w.w};
            #pragma unroll
            for (int i = 0; i < 4; i++)
                #pragma unroll
                for (int j = 0; j < 4; j++) acc[i][j] += pv[i] * wv[j];
        }
        float4 bv1 = *(const float4*)(b1 + head * 128 + db);
        float bb1[4] = {bv1.x, bv1.y, bv1.z, bv1.w};
        __syncthreads();   // previous head's phase3 done reading hS
        #pragma unroll
        for (int j = 0; j < 4; j++)
            #pragma unroll
            for (int i = 0; i < 4; i++)
                hS[db + j][nb + i] = gelu_exact(acc[i][j] + bb1[j]);
        __syncthreads();

        // ---- phase 2: h2 = gelu(h1 @ W2 + b2) ----
        #pragma unroll
        for (int i = 0; i < 4; i++)
            #pragma unroll
            for (int j = 0; j < 4; j++) acc[i][j] = 0.0f;

        for (int k = 0; k < 128; k++) {
            float4 w = *(const float4*)(w2 + k * 128 + db);
            float4 p = *(const float4*)(&hS[k][nb]);
            float pv[4] = {p.x, p.y, p.z, p.w};
            float wv[4] = {w.x, w.y, w.z, w.w};
            #pragma unroll
            for (int i = 0; i < 4; i++)
                #pragma unroll
                for (int j = 0; j < 4; j++) acc[i][j] += pv[i] * wv[j];
        }
        float4 bv2 = *(const float4*)(b2 + head * 128 + db);
        float bb2[4] = {bv2.x, bv2.y, bv2.z, bv2.w};
        __syncthreads();   // all threads done reading h1
        #pragma unroll
        for (int j = 0; j < 4; j++)
            #pragma unroll
            for (int i = 0; i < 4; i++)
                hS[db + j][nb + i] = gelu_exact(acc[i][j] + bb2[j]);
        __syncthreads();

        // ---- phase 3: head-specific output + activation ----
        if (head == 0) {
            for (int idx = t; idx < 64; idx += 256) {
                int n = idx >> 1, o = idx & 1;
                float s = 0.0f;
                for (int k = 0; k < 128; k++) s += hS[k][n] * spaceW3[k * 2 + o];
                outS[n][o] = s;
            }
            __syncthreads();
            if (t < 32 && n0 + t < N) {
                float gx = tanhf(outS[t][0]);
                float gy = tanhf(outS[t][1]);
                float x = (gx + 1.0f) * 8.0f - 0.5f;
                float y = (gy + 1.0f) * 8.0f - 0.5f;
                float x0f = floorf(x), y0f = floorf(y);
                float wx = x - x0f, wy = y - y0f;
                int x0 = (int)x0f, y0 = (int)y0f;
                int x1 = x0 + 1, y1 = y0 + 1;
                float vx0 = (x0 >= 0 && x0 < 16) ? 1.0f : 0.0f;
                float vx1 = (x1 >= 0 && x1 < 16) ? 1.0f : 0.0f;
                float vy0 = (y0 >= 0 && y0 < 16) ? 1.0f : 0.0f;
                float vy1 = (y1 >= 0 && y1 < 16) ? 1.0f : 0.0f;
                int cx0 = min(max(x0, 0), 15), cx1 = min(max(x1, 0), 15);
                int cy0 = min(max(y0, 0), 15), cy1 = min(max(y1, 0), 15);
                int nn = n0 + t;
                d_pixv[nn * 4 + 0] = cy0 * 16 + cx0;
                d_pixv[nn * 4 + 1] = cy0 * 16 + cx1;
                d_pixv[nn * 4 + 2] = cy1 * 16 + cx0;
                d_pixv[nn * 4 + 3] = cy1 * 16 + cx1;
                d_pwv[nn * 4 + 0] = (1.0f - wx) * (1.0f - wy) * vx0 * vy0;
                d_pwv[nn * 4 + 1] = wx * (1.0f - wy) * vx1 * vy0;
                d_pwv[nn * 4 + 2] = (1.0f - wx) * wy * vx0 * vy1;
                d_pwv[nn * 4 + 3] = wx * wy * vx1 * vy1;
            }
        } else if (head == 1) {
            for (int idx = t; idx < 384; idx += 256) {
                int n = idx / 12, o = idx - n * 12;
                float s = 0.0f;
                for (int k = 0; k < 128; k++) s += hS[k][n] * layerW3[k * 12 + o];
                outS[n][o] = s;
            }
            __syncthreads();
            if (t < 32) {
                float ent = 0.0f;
                if (n0 + t < N) {
                    float m = -1e30f;
                    #pragma unroll
                    for (int o = 0; o < 12; o++) m = fmaxf(m, outS[t][o]);
                    float e[12], sum = 0.0f;
                    #pragma unroll
                    for (int o = 0; o < 12; o++) { e[o] = expf(outS[t][o] - m); sum += e[o]; }
                    float inv = 1.0f / sum;
                    #pragma unroll
                    for (int o = 0; o < 12; o++) {
                        float p = e[o] * inv;
                        d_wl[(n0 + t) * 12 + o] = p;
                        ent += p * logf(p + 1e-8f);
                    }
                }
                entS[t] = ent;
            }
        } else {
            for (int idx = t; idx < 32; idx += 256) {
                float s = 0.0f;
                for (int k = 0; k < 128; k++) s += hS[k][idx] * scaleW3[k];
                outS[idx][0] = s;
            }
            __syncthreads();
            if (t < 32) {
                float pen = 0.0f;
                if (n0 + t < N) {
                    float sg = 1.0f / (1.0f + expf(-outS[t][0]));
                    d_sscale[n0 + t] = sg;
                    float dd = sg - 0.5f;
                    pen = dd * dd;
                }
                penS[t] = pen;
            }
        }
    }

    __syncthreads();
    if (t == 0) {
        float se = 0.0f, sp = 0.0f;
        #pragma unroll
        for (int i = 0; i < 32; i++) { se += entS[i]; sp += penS[i]; }
        atomicAdd(&d_regE, se);
        atomicAdd(&d_regS, sp);
    }
}

// ---------------- gb[l,b,d] = sum_c global_tokens[l,b,c] * glob_w[l,d,c] ----------------
__global__ __launch_bounds__(128) void gb_kernel(
    const float* __restrict__ gt, const float* __restrict__ gw)
{
    int lb = blockIdx.x;                // 0..47
    int l = lb >> 2, b = lb & 3;
    __shared__ float gS[CC];
    int t = threadIdx.x;
    for (int i = t; i < CC; i += 128) gS[i] = gt[(l * BB + b) * CC + i];
    __syncthreads();
    int warp = t >> 5, lane = t & 31;
    for (int dd = 0; dd < 32; dd++) {
        int d = warp * 32 + dd;
        const float* wr = gw + ((size_t)(l * DD + d)) * CC;
        float s = 0.0f;
        for (int c = lane; c < CC; c += 32) s += gS[c] * wr[c];
        #pragma unroll
        for (int o = 16; o; o >>= 1) s += __shfl_xor_sync(0xFFFFFFFFu, s, o);
        if (lane == 0) d_gb[(l * BB + b) * DD + d] = s;
    }
}

// ---------------- conv feats: feat[l,b,p,d] = sum_c lt[l,b,c,p] * cw[l,d,c] ----------------
__global__ __launch_bounds__(256) void conv_kernel(
    const float* __restrict__ lt, const float* __restrict__ cw)
{
    __shared__ __align__(16) float imgS[32][68];   // [c][p] tile (64 p, padded)
    __shared__ float cwS[128][33];                 // [d][c] tile

    int bid = blockIdx.x;               // 192 blocks = 48 (l,b) * 4 p-tiles
    int lb = bid >> 2;
    int p0 = (bid & 3) * 64;
    int l = lb >> 2, b = lb & 3;
    const float* img = lt + ((size_t)(l * BB + b)) * CC * HWN;   // [C][256]
    const float* w = cw + ((size_t)l) * DD * CC;                 // [128][768]

    const int t = threadIdx.x;
    const int pcol = (t & 15) * 4;      // 4 of 64 pixels
    const int drow = (t >> 4) * 8;      // 8 of 128 dims

    float acc[4][8];
    #pragma unroll
    for (int i = 0; i < 4; i++)
        #pragma unroll
        for (int j = 0; j < 8; j++) acc[i][j] = 0.0f;

    for (int c0 = 0; c0 < CC; c0 += 32) {
        for (int idx = t; idx < 32 * 64; idx += 256) {
            int ccx = idx >> 6, pp = idx & 63;
            imgS[ccx][pp] = img[(size_t)(c0 + ccx) * HWN + p0 + pp];
        }
        for (int idx = t; idx < 128 * 32; idx += 256) {
            int d = idx >> 5, ccx = idx & 31;
            cwS[d][ccx] = w[(size_t)d * CC + c0 + ccx];
        }
        __syncthreads();
        #pragma unroll
        for (int kk = 0; kk < 32; kk++) {
            float4 pv4 = *(const float4*)(&imgS[kk][pcol]);
            float pv[4] = {pv4.x, pv4.y, pv4.z, pv4.w};
            float wv[8];
            #pragma unroll
            for (int j = 0; j < 8; j++) wv[j] = cwS[drow + j][kk];
            #pragma unroll
            for (int i = 0; i < 4; i++)
                #pragma unroll
                for (int j = 0; j < 8; j++) acc[i][j] += pv[i] * wv[j];
        }
        __syncthreads();
    }
    #pragma unroll
    for (int i = 0; i < 4; i++)
        #pragma unroll
        for (int j = 0; j < 8; j++)
            d_feat[((size_t)lb * HWN + p0 + pcol + i) * DD + drow + j] = acc[i][j];
}

// ---------------- final: gather + bilinear + layer mix + global mix + out-weight dot ----------------
__global__ __launch_bounds__(256) void final_kernel(
    const float* __restrict__ ow, const float* __restrict__ ob,
    float* __restrict__ out, int N, int out_size)
{
    __shared__ __align__(16) float gbS[LL * BB * DD];   // 24.6 KB
    int t = threadIdx.x;
    for (int i = t; i < LL * BB * DD; i += 256) gbS[i] = d_gb[i];
    __syncthreads();

    if (blockIdx.x == 0 && t == 0 && out_size > BB * N) {
        float reg = d_regE / ((float)N * logf(12.0f)) + d_regS / (float)N;
        out[BB * N] = reg;
    }

    int warp = t >> 5, lane = t & 31;
    int n = blockIdx.x * 8 + warp;
    if (n >= N) return;

    float4 ow4 = *(const float4*)(ow + (size_t)n * DD + lane * 4);
    float wl[12];
    #pragma unroll
    for (int l = 0; l < 12; l++) wl[l] = d_wl[n * 12 + l];
    int pix[4]; float pw[4];
    #pragma unroll
    for (int c = 0; c < 4; c++) { pix[c] = d_pixv[n * 4 + c]; pw[c] = d_pwv[n * 4 + c]; }
    float s = d_sscale[n];
    float bias = ob[n];
    const float4* feat4 = reinterpret_cast<const float4*>(d_feat);

    #pragma unroll
    for (int b = 0; b < 4; b++) {
        float aLx = 0, aLy = 0, aLz = 0, aLw = 0;
        float aGx = 0, aGy = 0, aGz = 0, aGw = 0;
        #pragma unroll
        for (int l = 0; l < 12; l++) {
            float cl = wl[l];
            int base = (l * BB + b) * HWN;
            #pragma unroll
            for (int c = 0; c < 4; c++) {
                float coef = cl * pw[c];
                float4 f = feat4[(size_t)(base + pix[c]) * 32 + lane];
                aLx += coef * f.x; aLy += coef * f.y;
                aLz += coef * f.z; aLw += coef * f.w;
            }
            float4 g = *(const float4*)(&gbS[(l * BB + b) * DD + lane * 4]);
            aGx += cl * g.x; aGy += cl * g.y; aGz += cl * g.z; aGw += cl * g.w;
        }
        float os = 1.0f - s;
        float vx = os * aLx + s * aGx;
        float vy = os * aLy + s * aGy;
        float vz = os * aLz + s * aGz;
        float vw = os * aLw + s * aGw;
        float part = vx * ow4.x + vy * ow4.y + vz * ow4.z + vw * ow4.w;
        #pragma unroll
        for (int o = 16; o; o >>= 1) part += __shfl_xor_sync(0xFFFFFFFFu, part, o);
        if (lane == 0) out[b * N + n] = part * (1.0f / 128.0f) + bias;
    }
}

// ---------------- launch ----------------
extern "C" void kernel_launch(void* const* d_in, const int* in_sizes, int n_in,
                              void* d_out, int out_size) {
    const float* lt      = (const float*)d_in[0];
    const float* gt      = (const float*)d_in[1];
    const float* coords  = (const float*)d_in[2];
    const float* conv_w  = (const float*)d_in[3];
    const float* glob_w  = (const float*)d_in[4];
    const float* W1      = (const float*)d_in[5];
    const float* b1      = (const float*)d_in[6];
    const float* W2      = (const float*)d_in[7];
    const float* b2      = (const float*)d_in[8];
    const float* spaceW3 = (const float*)d_in[9];
    const float* layerW3 = (const float*)d_in[10];
    const float* scaleW3 = (const float*)d_in[11];
    const float* ow      = (const float*)d_in[12];
    const float* ob      = (const float*)d_in[13];
    int N = in_sizes[2] / 3;
    float* out = (float*)d_out;

    init_kernel<<<1, 1>>>();
    selector_kernel<<<(N + 31) / 32, 256>>>(coords, W1, b1, W2, b2,
                                            spaceW3, layerW3, scaleW3, N);
    gb_kernel<<<48, 128>>>(gt, glob_w);
    conv_kernel<<<192, 256>>>(lt, conv_w);
    final_kernel<<<(N + 7) / 8, 256>>>(ow, ob, out, N, out_size);
}